// round 14
// baseline (speedup 1.0000x reference)
#include <cuda_runtime.h>

// out[i, h=n*7+o, m] = sum_{j<48,k<3} W[i,j*3+k] * x[j, n*7+(o+k-1), m]
//   (term dropped when o+k-1 outside [0,7))
// x: (48,56,56) f32   W: (192,48,3) f32   out: (192,56,56) f32
//
// R13 + __launch_bounds__(128,1) (release ptxas reg cap; smem already limits
// residency to 2 blocks/SM) + explicit double-buffered x prefetch across the
// 4j t-groups so LDS latency hides behind the previous group's 144 FFMAs.

#define JCH 48
#define KTAP 3
#define MW 56
#define MP 64            // padded m
#define BI 32            // output channels per block
#define NTHREADS 128
#define NQ 36            // f4 chunks along jk (144/4)
#define WROW 33          // ws4 row stride in float4 (odd -> conflict-free STS)

__global__ __launch_bounds__(NTHREADS, 1)
void fold_conv_kernel(const float* __restrict__ x,
                      const float* __restrict__ W,
                      float* __restrict__ out)
{
    extern __shared__ float sm[];
    float*  xs  = sm;                              // [KTAP*JCH][MP] f32 (36 KB)
    float4* ws4 = (float4*)(sm + KTAP * JCH * MP); // [NQ][WROW] f4  (19 KB)

    const int tid = threadIdx.x;
    const int h  = blockIdx.x;              // 0..55
    const int n  = h / 7;
    const int o  = h - n * 7;
    const int i0 = blockIdx.y * BI;         // 0..160 step 32

    // ---- x slab: 144 rows x 16 float4, coalesced, zero-padded ----
    {
        float4* xs4 = (float4*)xs;
        #pragma unroll
        for (int it = 0; it < (KTAP * JCH * 16) / NTHREADS; ++it) {   // 18 iters
            int idx = tid + it * NTHREADS;          // 0..2303
            int row = idx >> 4;                     // k*48+j
            int s   = idx & 15;                     // float4 slot
            int k   = row / JCH;
            int j   = row - k * JCH;
            int r   = o + k - 1;
            float4 v = make_float4(0.f, 0.f, 0.f, 0.f);
            if (r >= 0 && r < 7 && s < 14)
                v = *(const float4*)&x[(j * 56 + n * 7 + r) * 56 + s * 4];
            xs4[idx] = v;
        }
    }
    // ---- W tile: f4 gmem reads (coalesced), STS f4 to ws4[q][ii] ----
    #pragma unroll
    for (int it = 0; it < (BI * NQ) / NTHREADS; ++it) {   // 9 iters
        int idx = tid + it * NTHREADS;               // 0..1151
        int ii  = idx / NQ;
        int q   = idx - ii * NQ;
        float4 v = *(const float4*)&W[(i0 + ii) * (JCH * KTAP) + q * 4];
        ws4[q * WROW + ii] = v;                      // q+1 -> +33 f4 -> bank+4
    }
    __syncthreads();

    // ---- mainloop: thread computes i in {i0+ig+8a} x 4m, 4j per t-group ----
    const int ig = tid & 7;                 // 8 i-groups (strided i)
    const int mg = tid >> 3;                // 16 m-groups
    const int m0 = mg * 4;                  // mg 14,15 hit padding (discarded)

    float acc[4][4];
    #pragma unroll
    for (int a = 0; a < 4; ++a)
        #pragma unroll
        for (int b = 0; b < 4; ++b)
            acc[a][b] = 0.0f;

    float4 xv[2][12];                       // double-buffered x (96 regs)
    #pragma unroll
    for (int e = 0; e < 12; ++e) {          // prefetch t=0
        const int row = (e % 3) * JCH + e / 3;
        xv[0][e] = *(const float4*)&xs[row * MP + m0];
    }

    #pragma unroll 1
    for (int t = 0; t < 12; ++t) {          // 4 j per group
        const int cur = t & 1;
        const int nxt = cur ^ 1;

        // W: 3 chunks x 4 a-rows, conflict-free LDS.128
        float4 wv[3][4];
        #pragma unroll
        for (int c = 0; c < 3; ++c)
            #pragma unroll
            for (int a = 0; a < 4; ++a)
                wv[c][a] = ws4[(3 * t + c) * WROW + a * 8 + ig];

        // prefetch next group's x while computing this one
        if (t < 11) {
            #pragma unroll
            for (int e = 0; e < 12; ++e) {
                const int row = (e % 3) * JCH + 4 * (t + 1) + e / 3;
                xv[nxt][e] = *(const float4*)&xs[row * MP + m0];
            }
        }

        #pragma unroll
        for (int c = 0; c < 3; ++c) {
            #pragma unroll
            for (int s = 0; s < 4; ++s) {
                const int e = 4 * c + s;
                const float xr[4] = {xv[cur][e].x, xv[cur][e].y,
                                     xv[cur][e].z, xv[cur][e].w};
                #pragma unroll
                for (int a = 0; a < 4; ++a) {
                    const float w = (s == 0) ? wv[c][a].x :
                                    (s == 1) ? wv[c][a].y :
                                    (s == 2) ? wv[c][a].z : wv[c][a].w;
                    acc[a][0] = fmaf(w, xr[0], acc[a][0]);
                    acc[a][1] = fmaf(w, xr[1], acc[a][1]);
                    acc[a][2] = fmaf(w, xr[2], acc[a][2]);
                    acc[a][3] = fmaf(w, xr[3], acc[a][3]);
                }
            }
        }
    }

    // ---- store (skip padded m-groups; 16B-aligned float4) ----
    if (m0 < MW) {
        #pragma unroll
        for (int a = 0; a < 4; ++a) {
            const int i = i0 + ig + a * 8;
            float4 v = {acc[a][0], acc[a][1], acc[a][2], acc[a][3]};
            *(float4*)&out[i * 3136 + h * 56 + m0] = v;
        }
    }
}

extern "C" void kernel_launch(void* const* d_in, const int* in_sizes, int n_in,
                              void* d_out, int out_size)
{
    const float* x = (const float*)d_in[0];   // 48*56*56
    const float* W = (const float*)d_in[1];   // 192*48*3
    float* out = (float*)d_out;               // 192*56*56

    const int smem = (KTAP * JCH * MP) * 4 + NQ * WROW * 16; // 55872 B
    static bool attr_set = false;
    if (!attr_set) {
        cudaFuncSetAttribute(fold_conv_kernel,
                             cudaFuncAttributeMaxDynamicSharedMemorySize, smem);
        attr_set = true;
    }
    dim3 grid(56, 6);
    fold_conv_kernel<<<grid, NTHREADS, smem>>>(x, W, out);
}

// round 15
// speedup vs baseline: 1.8294x; 1.8294x over previous
#include <cuda_runtime.h>

// out[i, h=n*7+o, m] = sum_{j<48,k<3} W[i,j*3+k] * x[j, n*7+(o+k-1), m]
//   (term dropped when o+k-1 outside [0,7))
// x: (48,56,56) f32   W: (192,48,3) f32   out: (192,56,56) f32
//
// Split-j: 256 threads = two 128-thread halves; each half computes the SAME
// 4i x 4m output tiles over half of the j range (24 j), partials combined
// through smem. One x slab per block (no duplication), 2x warp pressure.
// Mainloop = R13's conflict-free vectorized form.

#define JCH 48
#define KTAP 3
#define MW 56
#define MP 64            // padded m
#define BI 32            // output channels per block
#define NTHREADS 256
#define NQ 36            // f4 chunks along jk (144/4)
#define WROW 33          // ws4 row stride in float4 (odd -> conflict-free STS)

__global__ __launch_bounds__(NTHREADS, 2)
void fold_conv_kernel(const float* __restrict__ x,
                      const float* __restrict__ W,
                      float* __restrict__ out)
{
    extern __shared__ float sm[];
    float*  xs  = sm;                              // [KTAP*JCH][MP] f32 (36 KB)
    float4* ws4 = (float4*)(sm + KTAP * JCH * MP); // [NQ][WROW] f4  (19 KB)

    const int tid = threadIdx.x;
    const int h  = blockIdx.x;              // 0..55
    const int n  = h / 7;
    const int o  = h - n * 7;
    const int i0 = blockIdx.y * BI;         // 0..160 step 32

    // ---- x slab: 144 rows x 16 float4, coalesced, zero-padded ----
    {
        float4* xs4 = (float4*)xs;
        #pragma unroll
        for (int it = 0; it < (KTAP * JCH * 16) / NTHREADS; ++it) {   // 9 iters
            int idx = tid + it * NTHREADS;          // 0..2303
            int row = idx >> 4;                     // k*48+j
            int s   = idx & 15;                     // float4 slot
            int k   = row / JCH;
            int j   = row - k * JCH;
            int r   = o + k - 1;
            float4 v = make_float4(0.f, 0.f, 0.f, 0.f);
            if (r >= 0 && r < 7 && s < 14)
                v = *(const float4*)&x[(j * 56 + n * 7 + r) * 56 + s * 4];
            xs4[idx] = v;
        }
    }
    // ---- W tile: f4 gmem reads (coalesced), STS f4 to ws4[q][ii] ----
    #pragma unroll
    for (int it = 0; it < 5; ++it) {                 // ceil(1152/256)
        int idx = tid + it * NTHREADS;               // 0..1151
        if (idx < BI * NQ) {
            int ii = idx / NQ;
            int q  = idx - ii * NQ;
            float4 v = *(const float4*)&W[(i0 + ii) * (JCH * KTAP) + q * 4];
            ws4[q * WROW + ii] = v;                  // q+1 -> +33 f4 -> bank+4
        }
    }
    __syncthreads();

    // ---- mainloop: two halves, each 6 t-groups (24 j) over same tiles ----
    const int half   = tid >> 7;            // 0: j 0..23, 1: j 24..47
    const int wg_tid = tid & 127;
    const int ig = wg_tid & 7;              // 8 i-groups (strided i)
    const int mg = wg_tid >> 3;             // 16 m-groups
    const int m0 = mg * 4;                  // mg 14,15 hit padding (discarded)

    float acc[4][4];
    #pragma unroll
    for (int a = 0; a < 4; ++a)
        #pragma unroll
        for (int b = 0; b < 4; ++b)
            acc[a][b] = 0.0f;

    const int t0 = half * 6;
    #pragma unroll 1
    for (int u = 0; u < 6; ++u) {           // 4 j per t-group
        const int t = t0 + u;
        // W: 3 chunks x 4 a-rows, conflict-free LDS.128
        float4 wv[3][4];
        #pragma unroll
        for (int c = 0; c < 3; ++c)
            #pragma unroll
            for (int a = 0; a < 4; ++a)
                wv[c][a] = ws4[(3 * t + c) * WROW + a * 8 + ig];
        // x: 12 rows (jk = 12t+e -> k = e%3, j = 4t + e/3), 1-wavefront LDS.128
        float4 xv[12];
        #pragma unroll
        for (int e = 0; e < 12; ++e) {
            const int row = (e % 3) * JCH + 4 * t + e / 3;
            xv[e] = *(const float4*)&xs[row * MP + m0];
        }
        #pragma unroll
        for (int c = 0; c < 3; ++c) {
            #pragma unroll
            for (int s = 0; s < 4; ++s) {
                const int e = 4 * c + s;
                const float xr[4] = {xv[e].x, xv[e].y, xv[e].z, xv[e].w};
                #pragma unroll
                for (int a = 0; a < 4; ++a) {
                    const float w = (s == 0) ? wv[c][a].x :
                                    (s == 1) ? wv[c][a].y :
                                    (s == 2) ? wv[c][a].z : wv[c][a].w;
                    acc[a][0] = fmaf(w, xr[0], acc[a][0]);
                    acc[a][1] = fmaf(w, xr[1], acc[a][1]);
                    acc[a][2] = fmaf(w, xr[2], acc[a][2]);
                    acc[a][3] = fmaf(w, xr[3], acc[a][3]);
                }
            }
        }
    }

    // ---- combine halves through smem (reuse xs region), half 0 stores ----
    __syncthreads();                        // all mainloop LDS done
    {
        float* osm = sm;                    // [128][16] floats (8 KB)
        if (half == 1) {
            #pragma unroll
            for (int a = 0; a < 4; ++a)
                *(float4*)&osm[wg_tid * 16 + a * 4] =
                    make_float4(acc[a][0], acc[a][1], acc[a][2], acc[a][3]);
        }
        __syncthreads();
        if (half == 0 && m0 < MW) {
            #pragma unroll
            for (int a = 0; a < 4; ++a) {
                const float4 p = *(const float4*)&osm[wg_tid * 16 + a * 4];
                const int i = i0 + ig + a * 8;
                float4 v = {acc[a][0] + p.x, acc[a][1] + p.y,
                            acc[a][2] + p.z, acc[a][3] + p.w};
                *(float4*)&out[i * 3136 + h * 56 + m0] = v;
            }
        }
    }
}

extern "C" void kernel_launch(void* const* d_in, const int* in_sizes, int n_in,
                              void* d_out, int out_size)
{
    const float* x = (const float*)d_in[0];   // 48*56*56
    const float* W = (const float*)d_in[1];   // 192*48*3
    float* out = (float*)d_out;               // 192*56*56

    const int smem = (KTAP * JCH * MP) * 4 + NQ * WROW * 16; // 55872 B
    static bool attr_set = false;
    if (!attr_set) {
        cudaFuncSetAttribute(fold_conv_kernel,
                             cudaFuncAttributeMaxDynamicSharedMemorySize, smem);
        attr_set = true;
    }
    dim3 grid(56, 6);
    fold_conv_kernel<<<grid, NTHREADS, smem>>>(x, W, out);
}

// round 16
// speedup vs baseline: 2.4694x; 1.3499x over previous
#include <cuda_runtime.h>
#include <cuda_bf16.h>
#include <cstdint>

// out[i, h, m] = sum_{j<48,k<3} W[i,j*3+k] * xpad[j,h,k,m]
// GEMM: D[i, pos] = sum_kk W[i,kk] * X[kk,pos],  kk=j*3+k (K=144),
//       pos = hl*64+m for an h-pair (M_pos=128), i-tile of 48.
// bf16 split: v = hi+lo; D = Wh*Xh + Wh*Xl + Wl*Xh (fp32 accum via mma.sync).

#define XST 136   // X row stride (bf16): 272B, 16B-aligned; ldmatrix rows conflict-free
#define WST 152   // W row stride (bf16): 304B, 16B-aligned; conflict-free
#define NTHREADS 256

#define SM_XHI 0
#define SM_XLO (144 * XST * 2)              // 39168
#define SM_WHI (2 * 144 * XST * 2)          // 78336
#define SM_WLO (SM_WHI + 48 * WST * 2)      // 92928
#define SM_TOTAL (SM_WLO + 48 * WST * 2)    // 107520 B

__device__ __forceinline__ uint32_t smem_u32(const void* p) {
    uint32_t a;
    asm("{ .reg .u64 t; cvta.to.shared.u64 t, %1; cvt.u32.u64 %0, t; }" : "=r"(a) : "l"(p));
    return a;
}
__device__ __forceinline__ uint32_t pk(__nv_bfloat16 a, __nv_bfloat16 b) {
    return (uint32_t)__bfloat16_as_ushort(a) | ((uint32_t)__bfloat16_as_ushort(b) << 16);
}

#define LDMX4(r, addr) \
    asm volatile("ldmatrix.sync.aligned.m8n8.x4.shared.b16 {%0,%1,%2,%3}, [%4];" \
                 : "=r"((r)[0]), "=r"((r)[1]), "=r"((r)[2]), "=r"((r)[3]) : "r"(addr))
#define LDMX2T(r, addr) \
    asm volatile("ldmatrix.sync.aligned.m8n8.x2.trans.shared.b16 {%0,%1}, [%2];" \
                 : "=r"((r)[0]), "=r"((r)[1]) : "r"(addr))
#define MMA(d, a, b) \
    asm volatile("mma.sync.aligned.m16n8k16.row.col.f32.bf16.bf16.f32 " \
                 "{%0,%1,%2,%3}, {%4,%5,%6,%7}, {%8,%9}, {%0,%1,%2,%3};" \
                 : "+f"((d)[0]), "+f"((d)[1]), "+f"((d)[2]), "+f"((d)[3]) \
                 : "r"((a)[0]), "r"((a)[1]), "r"((a)[2]), "r"((a)[3]), \
                   "r"((b)[0]), "r"((b)[1]))

__global__ __launch_bounds__(NTHREADS, 1)
void fold_conv_mma(const float* __restrict__ x,
                   const float* __restrict__ W,
                   float* __restrict__ out)
{
    extern __shared__ char smem[];
    __nv_bfloat16* xhi = (__nv_bfloat16*)(smem + SM_XHI);
    __nv_bfloat16* xlo = (__nv_bfloat16*)(smem + SM_XLO);
    __nv_bfloat16* whi = (__nv_bfloat16*)(smem + SM_WHI);
    __nv_bfloat16* wlo = (__nv_bfloat16*)(smem + SM_WLO);

    const int tid = threadIdx.x;
    const int hb  = blockIdx.x;             // 0..27 (h pair)
    const int i0  = blockIdx.y * 48;        // 0..144 step 48

    // ---- build X[kk][pos] hi/lo: idx = ((k*48+j)*2+hl)*8+oct, f4-coalesced ----
    #pragma unroll
    for (int it = 0; it < 9; ++it) {
        int idx = tid + it * NTHREADS;      // < 2304
        int oct = idx & 7;
        int hl  = (idx >> 3) & 1;
        int js  = idx >> 4;                 // k*48+j
        int k   = js / 48;
        int j   = js - k * 48;
        int h   = 2 * hb + hl;
        int o   = h % 7;
        int m0  = oct * 8;
        float4 v0 = make_float4(0.f, 0.f, 0.f, 0.f), v1 = v0;
        int r = o + k - 1;
        if (r >= 0 && r < 7 && oct < 7) {   // x row index = h+k-1 when r valid
            const float* src = x + (j * 56 + (h + k - 1)) * 56 + m0;
            v0 = *(const float4*)src;
            v1 = *(const float4*)(src + 4);
        }
        const float vv[8] = {v0.x, v0.y, v0.z, v0.w, v1.x, v1.y, v1.z, v1.w};
        __nv_bfloat16 hi8[8], lo8[8];
        #pragma unroll
        for (int e = 0; e < 8; ++e) {
            hi8[e] = __float2bfloat16_rn(vv[e]);
            lo8[e] = __float2bfloat16_rn(vv[e] - __bfloat162float(hi8[e]));
        }
        int off = (j * 3 + k) * XST + hl * 64 + m0;
        uint4 ph = {pk(hi8[0], hi8[1]), pk(hi8[2], hi8[3]), pk(hi8[4], hi8[5]), pk(hi8[6], hi8[7])};
        uint4 pl = {pk(lo8[0], lo8[1]), pk(lo8[2], lo8[3]), pk(lo8[4], lo8[5]), pk(lo8[6], lo8[7])};
        *(uint4*)&xhi[off] = ph;
        *(uint4*)&xlo[off] = pl;
    }
    // ---- build W[ii][kk] hi/lo ----
    #pragma unroll
    for (int it = 0; it < 4; ++it) {
        int idx = tid + it * NTHREADS;
        if (idx < 48 * 18) {
            int ii  = idx / 18;
            int oct = idx - ii * 18;
            int kk0 = oct * 8;
            const float* src = W + (i0 + ii) * 144 + kk0;
            float4 v0 = *(const float4*)src, v1 = *(const float4*)(src + 4);
            const float vv[8] = {v0.x, v0.y, v0.z, v0.w, v1.x, v1.y, v1.z, v1.w};
            __nv_bfloat16 hi8[8], lo8[8];
            #pragma unroll
            for (int e = 0; e < 8; ++e) {
                hi8[e] = __float2bfloat16_rn(vv[e]);
                lo8[e] = __float2bfloat16_rn(vv[e] - __bfloat162float(hi8[e]));
            }
            int off = ii * WST + kk0;
            uint4 ph = {pk(hi8[0], hi8[1]), pk(hi8[2], hi8[3]), pk(hi8[4], hi8[5]), pk(hi8[6], hi8[7])};
            uint4 pl = {pk(lo8[0], lo8[1]), pk(lo8[2], lo8[3]), pk(lo8[4], lo8[5]), pk(lo8[6], lo8[7])};
            *(uint4*)&whi[off] = ph;
            *(uint4*)&wlo[off] = pl;
        }
    }
    __syncthreads();

    // ---- warp-level mma mainloop ----
    const int warp = tid >> 5;
    const int lane = tid & 31;
    const int lr16 = lane & 15;             // A: row within 16; B: k-row (lanes>=16 clamped)
    const int lc   = lane >> 4;             // A: k-col half
    const uint32_t sb = smem_u32(smem);

    uint32_t aHb[3], aLb[3];
    #pragma unroll
    for (int mt = 0; mt < 3; ++mt) {
        uint32_t roff = (uint32_t)((mt * 16 + lr16) * WST + lc * 8) * 2u;
        aHb[mt] = sb + SM_WHI + roff;
        aLb[mt] = sb + SM_WLO + roff;
    }
    uint32_t bHb[2], bLb[2];
    #pragma unroll
    for (int nti = 0; nti < 2; ++nti) {
        uint32_t boff = (uint32_t)(lr16 * XST + (warp * 2 + nti) * 8) * 2u;
        bHb[nti] = sb + SM_XHI + boff;
        bLb[nti] = sb + SM_XLO + boff;
    }

    float d[6][4];
    #pragma unroll
    for (int t = 0; t < 6; ++t)
        d[t][0] = d[t][1] = d[t][2] = d[t][3] = 0.f;

    #pragma unroll
    for (int c = 0; c < 9; ++c) {
        const uint32_t aoff = (uint32_t)c * 32u;          // 16 kk * 2B
        const uint32_t boff = (uint32_t)c * (16u * XST * 2u);
        uint32_t ah[3][4], al[3][4], bh[2][2], bl[2][2];
        #pragma unroll
        for (int mt = 0; mt < 3; ++mt) LDMX4(ah[mt], aHb[mt] + aoff);
        #pragma unroll
        for (int mt = 0; mt < 3; ++mt) LDMX4(al[mt], aLb[mt] + aoff);
        #pragma unroll
        for (int nti = 0; nti < 2; ++nti) LDMX2T(bh[nti], bHb[nti] + boff);
        #pragma unroll
        for (int nti = 0; nti < 2; ++nti) LDMX2T(bl[nti], bLb[nti] + boff);
        #pragma unroll
        for (int mt = 0; mt < 3; ++mt) {
            #pragma unroll
            for (int nti = 0; nti < 2; ++nti) {
                MMA(d[mt * 2 + nti], ah[mt], bh[nti]);
                MMA(d[mt * 2 + nti], ah[mt], bl[nti]);
                MMA(d[mt * 2 + nti], al[mt], bh[nti]);
            }
        }
    }

    // ---- epilogue: direct STG.64 (D rows = i, cols = pos) ----
    const int qr = lane >> 2;               // row 0..7 within m16
    const int qc = (lane & 3) * 2;          // col pair
    #pragma unroll
    for (int mt = 0; mt < 3; ++mt) {
        #pragma unroll
        for (int nti = 0; nti < 2; ++nti) {
            const float* dd = d[mt * 2 + nti];
            int posb = (warp * 2 + nti) * 8 + qc;
            int hl = posb >> 6;
            int mm = posb & 63;
            if (mm < 56) {
                int i = i0 + mt * 16 + qr;
                int h = 2 * hb + hl;
                float* p = out + i * 3136 + h * 56 + mm;
                *(float2*)p = make_float2(dd[0], dd[1]);
                *(float2*)(p + 8 * 3136) = make_float2(dd[2], dd[3]);
            }
        }
    }
}

extern "C" void kernel_launch(void* const* d_in, const int* in_sizes, int n_in,
                              void* d_out, int out_size)
{
    const float* x = (const float*)d_in[0];   // 48*56*56
    const float* W = (const float*)d_in[1];   // 192*48*3
    float* out = (float*)d_out;               // 192*56*56

    static bool attr_set = false;
    if (!attr_set) {
        cudaFuncSetAttribute(fold_conv_mma,
                             cudaFuncAttributeMaxDynamicSharedMemorySize, SM_TOTAL);
        attr_set = true;
    }
    dim3 grid(28, 4);
    fold_conv_mma<<<grid, NTHREADS, SM_TOTAL>>>(x, W, out);
}